// round 17
// baseline (speedup 1.0000x reference)
#include <cuda_runtime.h>

// Fused antialiased bilinear resize: (2,3,345,456) -> (2,3,271,272), fp32.
//   horizontal: 456 -> 272 (scale 456/272), vertical: 345 -> 271 (scale 345/271)
// One CTA = (channel, block of 8 output rows). Phase 1 h-filters the needed
// input rows into smem; phase 2 v-filters smem -> gmem (float4).
#define H_IN  345
#define W_IN  456
#define H_OUT 271
#define W_OUT 272
#define W_OUT4 68
#define NCH   6
#define KS    5
#define YB    8            // output rows per CTA
#define SROWS 16           // smem rows (vertical support span <= 14)

#define SCALE_W ((float)(456.0 / 272.0))
#define INV_W   ((float)(272.0 / 456.0))
#define SCALE_H ((float)(345.0 / 271.0))
#define INV_H   ((float)(271.0 / 345.0))

// Triangle-filter taps matching the aten decomposition: truncating int cast,
// clamp bounds, tap masking by window size, per-pixel weight normalization.
__device__ __forceinline__ void taps(int o, float scale, float invscale, int in_size,
                                     int idx[KS], float w[KS]) {
    float center = ((float)o + 0.5f) * scale;
    int xmin = max((int)(center - scale + 0.5f), 0);   // trunc toward zero == astype(int64)
    int xmax = min((int)(center + scale + 0.5f), in_size);
    int size = min(xmax - xmin, KS);
    float sum = 0.0f;
#pragma unroll
    for (int j = 0; j < KS; j++) {
        float ww = 1.0f - fminf(fabsf(((float)(j + xmin) - center + 0.5f) * invscale), 1.0f);
        ww = (j < size) ? ww : 0.0f;
        w[j] = ww;
        sum += ww;
        idx[j] = min(j + xmin, in_size - 1);
    }
    float rs = 1.0f / sum;
#pragma unroll
    for (int j = 0; j < KS; j++) w[j] *= rs;
}

__device__ __forceinline__ int vxmin(int y) {
    float center = ((float)y + 0.5f) * SCALE_H;
    return max((int)(center - SCALE_H + 0.5f), 0);
}

__global__ __launch_bounds__(256) void fused_resize_kernel(
    const float* __restrict__ in, float* __restrict__ out) {
    __shared__ __align__(16) float s_mid[SROWS * W_OUT];

    int c  = blockIdx.x;           // 0..5
    int yb = blockIdx.y;           // 0..33
    int y0 = yb * YB;
    int tid = threadIdx.y * 32 + threadIdx.x;

    // CTA-uniform vertical support window [rmin, rmax]
    int rmin  = vxmin(y0);
    int ylast = min(y0 + YB - 1, H_OUT - 1);
    int rmax  = min(vxmin(ylast) + KS - 1, H_IN - 1);
    int nrows = rmax - rmin + 1;   // <= 14

    const float* plane = in + c * (H_IN * W_IN);

    // ---- Phase 1: horizontal pass for rows rmin..rmax into smem ----
    for (int x = tid; x < W_OUT; x += 256) {
        int hidx[KS]; float hw[KS];
        taps(x, SCALE_W, INV_W, W_IN, hidx, hw);
        for (int s = 0; s < nrows; s++) {
            const float* row = plane + (rmin + s) * W_IN;
            float a = 0.0f;
#pragma unroll
            for (int j = 0; j < KS; j++)
                a = fmaf(__ldg(row + hidx[j]), hw[j], a);
            s_mid[s * W_OUT + x] = a;
        }
    }
    __syncthreads();

    // ---- Phase 2: vertical pass from smem, float4 stores ----
    int y = y0 + threadIdx.y;
    if (y < H_OUT) {
        int vidx[KS]; float vw[KS];
        taps(y, SCALE_H, INV_H, H_IN, vidx, vw);

        const float4* sm4 = reinterpret_cast<const float4*>(s_mid);
        float4* orow4 = reinterpret_cast<float4*>(out) + (c * H_OUT + y) * W_OUT4;

#pragma unroll
        for (int i = 0; i < 3; i++) {
            int col = threadIdx.x + i * 32;
            if (col < W_OUT4) {
                float4 a = make_float4(0.f, 0.f, 0.f, 0.f);
#pragma unroll
                for (int j = 0; j < KS; j++) {
                    float4 v = sm4[(vidx[j] - rmin) * W_OUT4 + col];
                    float wj = vw[j];
                    a.x = fmaf(v.x, wj, a.x);
                    a.y = fmaf(v.y, wj, a.y);
                    a.z = fmaf(v.z, wj, a.z);
                    a.w = fmaf(v.w, wj, a.w);
                }
                orow4[col] = a;
            }
        }
    }
}

extern "C" void kernel_launch(void* const* d_in, const int* in_sizes, int n_in,
                              void* d_out, int out_size) {
    const float* in = (const float*)d_in[0];
    float* out = (float*)d_out;
    dim3 block(32, 8, 1);
    dim3 grid(NCH, (H_OUT + YB - 1) / YB, 1);   // 6 x 34 = 204 CTAs
    fused_resize_kernel<<<grid, block>>>(in, out);
}